// round 17
// baseline (speedup 1.0000x reference)
#include <cuda_runtime.h>
#include <cuda_bf16.h>
#include <cstdint>

typedef unsigned long long ull;

// Problem constants
#define BB   256
#define TT   512
#define DD   300
#define HH   128
#define G4   512          // 4*H
#define CC   6
#define KP   320          // K padded

// ---------------- scratch (device globals: allocation-free) ----------------
__device__ float g_gx[(size_t)TT * BB * G4];                 // [t][b][g]
__device__ float g_h[BB * HH];                               // final hidden
// g_xhi/g_xlo stored in M-ORDER: row m = t*BB + b (matches g_gx)
__device__ __nv_bfloat16 g_xhi[(size_t)BB * TT * KP];
__device__ __nv_bfloat16 g_xlo[(size_t)BB * TT * KP];
__device__ __nv_bfloat16 g_whi[(size_t)G4 * KP];
__device__ __nv_bfloat16 g_wlo[(size_t)G4 * KP];

// ---------------- helpers ----------------
__device__ __forceinline__ ull fma2(ull a, ull b, ull c) {
    ull d;
    asm("fma.rn.f32x2 %0, %1, %2, %3;" : "=l"(d) : "l"(a), "l"(b), "l"(c));
    return d;
}
__device__ __forceinline__ ull pack2(float lo, float hi) {
    ull r;
    asm("mov.b64 %0, {%1, %2};" : "=l"(r) : "f"(lo), "f"(hi));
    return r;
}
__device__ __forceinline__ float sum2(ull v) {
    float lo, hi;
    asm("mov.b64 {%0, %1}, %2;" : "=f"(lo), "=f"(hi) : "l"(v));
    return lo + hi;
}
__device__ __forceinline__ float sigf(float x) { return 1.f / (1.f + __expf(-x)); }
__device__ __forceinline__ float tanhf_fast(float x) {
    float e = __expf(-2.f * fabsf(x));
    float r = (1.f - e) / (1.f + e);
    return copysignf(r, x);
}
__device__ __forceinline__ void cp16(void* smem_dst, const void* gsrc) {
    uint32_t sa = (uint32_t)__cvta_generic_to_shared(smem_dst);
    asm volatile("cp.async.cg.shared.global [%0], [%1], 16;\n" :: "r"(sa), "l"(gsrc));
}
__device__ __forceinline__ void cp_commit() { asm volatile("cp.async.commit_group;\n" ::: "memory"); }

// m16n8k16 bf16 mma, fp32 accum
__device__ __forceinline__ void mma16816(float* c, const uint32_t* a,
                                         uint32_t b0, uint32_t b1) {
    asm volatile(
        "mma.sync.aligned.m16n8k16.row.col.f32.bf16.bf16.f32 "
        "{%0,%1,%2,%3}, {%4,%5,%6,%7}, {%8,%9}, {%0,%1,%2,%3};"
        : "+f"(c[0]), "+f"(c[1]), "+f"(c[2]), "+f"(c[3])
        : "r"(a[0]), "r"(a[1]), "r"(a[2]), "r"(a[3]), "r"(b0), "r"(b1));
}

// ======================================================================
// Kernel 0: fp32 -> bf16 hi/lo precompute, zero-pad K to 320.
// ======================================================================
#define NXP ((size_t)BB * TT * (KP/2))
#define NWP ((size_t)G4 * (KP/2))

__global__ void __launch_bounds__(256) precvt_kernel(
    const float* __restrict__ x,
    const float* __restrict__ W_ih)
{
    size_t idx = (size_t)blockIdx.x * 256 + threadIdx.x;
    size_t total = NXP + NWP;
    if (idx >= total) return;

    const float* src;
    __nv_bfloat16 *dhi, *dlo;
    size_t kp;
    if (idx < NXP) {
        size_t row_lin = idx / (KP/2);
        kp = idx % (KP/2);
        size_t b = row_lin / TT;
        size_t t = row_lin % TT;
        size_t m = t * BB + b;
        src = x + row_lin * DD;
        dhi = g_xhi + m * KP; dlo = g_xlo + m * KP;
    } else {
        size_t j = idx - NXP;
        size_t row = j / (KP/2);
        kp = j % (KP/2);
        src = W_ih + row * DD;
        dhi = g_whi + row * KP; dlo = g_wlo + row * KP;
    }
    int kg = (int)kp * 2;
    float2 v = (kg < DD) ? *reinterpret_cast<const float2*>(src + kg) : make_float2(0.f, 0.f);
    __nv_bfloat16 h0 = __float2bfloat16(v.x);
    __nv_bfloat16 h1 = __float2bfloat16(v.y);
    __nv_bfloat16 l0 = __float2bfloat16(v.x - __bfloat162float(h0));
    __nv_bfloat16 l1 = __float2bfloat16(v.y - __bfloat162float(h1));
    uint32_t ph = (uint32_t)__bfloat16_as_ushort(h0) | ((uint32_t)__bfloat16_as_ushort(h1) << 16);
    uint32_t pl = (uint32_t)__bfloat16_as_ushort(l0) | ((uint32_t)__bfloat16_as_ushort(l1) << 16);
    *reinterpret_cast<uint32_t*>(dhi + kg) = ph;
    *reinterpret_cast<uint32_t*>(dlo + kg) = pl;
}

// ======================================================================
// Kernel 1: gx HMMA GEMM. Grid (N_tiles, M_tiles) for A-tile L2 reuse.
// ======================================================================
#define SSTR   40
#define ARR_B  (128 * SSTR * 2)
#define BUF_B  (4 * ARR_B)
#define SMEM_GX (2 * BUF_B + 512)

__global__ void __launch_bounds__(256, 2) gx_kernel(
    const float* __restrict__ b_ih,
    const float* __restrict__ b_hh)
{
    extern __shared__ char sm[];
    float* bsm = reinterpret_cast<float*>(sm + 2 * BUF_B);

    const int tid  = threadIdx.x;
    const int wid  = tid >> 5;
    const int lane = tid & 31;
    const int g    = lane >> 2;
    const int t4   = lane & 3;

    const int wr = wid & 3;
    const int wc = wid >> 2;

    const int n0  = blockIdx.x * 128;
    const int m0  = blockIdx.y * 128;

    if (tid < 128) bsm[tid] = b_ih[n0 + tid] + b_hh[n0 + tid];

    float acc[2][8][4];
#pragma unroll
    for (int mt = 0; mt < 2; ++mt)
#pragma unroll
        for (int nt = 0; nt < 8; ++nt)
#pragma unroll
            for (int r = 0; r < 4; ++r) acc[mt][nt][r] = 0.f;

    auto issue_slab = [&](int s, int buf) {
        char* base = sm + buf * BUF_B;
#pragma unroll
        for (int it = 0; it < 8; ++it) {
            int i   = it * 256 + tid;
            int arr = i >> 9;
            int r   = (i >> 2) & 127;
            int c   = i & 3;
            const __nv_bfloat16* gsrc;
            if (arr == 0)      gsrc = g_xhi + (size_t)(m0 + r) * KP;
            else if (arr == 1) gsrc = g_xlo + (size_t)(m0 + r) * KP;
            else if (arr == 2) gsrc = g_whi + (size_t)(n0 + r) * KP;
            else               gsrc = g_wlo + (size_t)(n0 + r) * KP;
            cp16(base + arr * ARR_B + (r * SSTR + c * 8) * 2,
                 reinterpret_cast<const char*>(gsrc) + s * 64 + c * 16);
        }
        cp_commit();
    };

    issue_slab(0, 0);

    for (int s = 0; s < 10; ++s) {
        if (s + 1 < 10) issue_slab(s + 1, (s + 1) & 1);
        if (s + 1 < 10) { asm volatile("cp.async.wait_group 1;\n" ::: "memory"); }
        else            { asm volatile("cp.async.wait_group 0;\n" ::: "memory"); }
        __syncthreads();

        char* base = sm + (s & 1) * BUF_B;
        __nv_bfloat16* Ahi = reinterpret_cast<__nv_bfloat16*>(base);
        __nv_bfloat16* Alo = reinterpret_cast<__nv_bfloat16*>(base + ARR_B);
        __nv_bfloat16* Bhi = reinterpret_cast<__nv_bfloat16*>(base + 2 * ARR_B);
        __nv_bfloat16* Blo = reinterpret_cast<__nv_bfloat16*>(base + 3 * ARR_B);

#pragma unroll
        for (int ks = 0; ks < 2; ++ks) {
            const int kb = ks * 16;
            uint32_t ahf[2][4], alf[2][4];
#pragma unroll
            for (int mt = 0; mt < 2; ++mt) {
                int r0 = (wr * 32 + mt * 16 + g) * SSTR + kb + t4 * 2;
                int r1 = r0 + 8 * SSTR;
                ahf[mt][0] = *reinterpret_cast<const uint32_t*>(&Ahi[r0]);
                ahf[mt][1] = *reinterpret_cast<const uint32_t*>(&Ahi[r1]);
                ahf[mt][2] = *reinterpret_cast<const uint32_t*>(&Ahi[r0 + 8]);
                ahf[mt][3] = *reinterpret_cast<const uint32_t*>(&Ahi[r1 + 8]);
                alf[mt][0] = *reinterpret_cast<const uint32_t*>(&Alo[r0]);
                alf[mt][1] = *reinterpret_cast<const uint32_t*>(&Alo[r1]);
                alf[mt][2] = *reinterpret_cast<const uint32_t*>(&Alo[r0 + 8]);
                alf[mt][3] = *reinterpret_cast<const uint32_t*>(&Alo[r1 + 8]);
            }
#pragma unroll
            for (int nt = 0; nt < 8; ++nt) {
                int br = (wc * 64 + nt * 8 + g) * SSTR + kb + t4 * 2;
                uint32_t bh0 = *reinterpret_cast<const uint32_t*>(&Bhi[br]);
                uint32_t bh1 = *reinterpret_cast<const uint32_t*>(&Bhi[br + 8]);
                uint32_t bl0 = *reinterpret_cast<const uint32_t*>(&Blo[br]);
                uint32_t bl1 = *reinterpret_cast<const uint32_t*>(&Blo[br + 8]);
#pragma unroll
                for (int mt = 0; mt < 2; ++mt) {
                    mma16816(acc[mt][nt], ahf[mt], bh0, bh1);
                    mma16816(acc[mt][nt], ahf[mt], bl0, bl1);
                    mma16816(acc[mt][nt], alf[mt], bh0, bh1);
                }
            }
        }
        __syncthreads();
    }

#pragma unroll
    for (int mt = 0; mt < 2; ++mt) {
#pragma unroll
        for (int nt = 0; nt < 8; ++nt) {
            int mrow = m0 + wr * 32 + mt * 16 + g;
            int nc   = wc * 64 + nt * 8 + t4 * 2;
            float b0v = bsm[nc], b1v = bsm[nc + 1];
            float2 v0 = make_float2(acc[mt][nt][0] + b0v, acc[mt][nt][1] + b1v);
            float2 v1 = make_float2(acc[mt][nt][2] + b0v, acc[mt][nt][3] + b1v);
            *reinterpret_cast<float2*>(&g_gx[(size_t)mrow * G4 + n0 + nc]) = v0;
            *reinterpret_cast<float2*>(&g_gx[(size_t)(mrow + 8) * G4 + n0 + nc]) = v1;
        }
    }
}

// ======================================================================
// Kernel 2: persistent LSTM -- WARP-INTERNAL j-reduction.
// 128 blocks x 2 batches, 512 threads (16 warps).
// Thread map: k = warp*8 + (lane&7), jg = lane>>3 (4 j-groups IN-warp).
// Partials reduced via shfl.bfly (xor 8, 16); elementwise on lanes 0-15
// (jg0->batch0, jg1->batch1) of EVERY warp; ONE barrier per step.
// Gates g,o in registers; gates i,f quad-layout smem (conflict-free).
// ======================================================================
#define OFF_WI4  0                            // [32 jq][128 k][4]
#define OFF_WF4  16384
#define OFF_HS3  32768                        // hs[2][2][128]
#define SMEM_LS  ((OFF_HS3 + 512) * 4)        // 133120 B

__global__ void __launch_bounds__(512, 1) lstm_kernel(
    const float* __restrict__ W_hh,
    const int*   __restrict__ lengths)
{
    extern __shared__ float smf[];
    float* Wi4 = smf + OFF_WI4;
    float* Wf4 = smf + OFF_WF4;
    float* hs  = smf + OFF_HS3;

    const int tid  = threadIdx.x;
    const int w    = tid >> 5;
    const int lane = tid & 31;
    const int jg   = lane >> 3;         // j-group 0..3 (in-warp)
    const int k    = w * 8 + (lane & 7); // hidden unit 0..127
    const int jb   = jg * 32;
    const int jbq  = jg * 8;
    const int b0   = blockIdx.x * 2;

    // stage quad-layout W for gates i, f
    for (int idx = tid; idx < 4096; idx += 512) {
        int jq = idx >> 7;
        int kk = idx & 127;
        float4 vi = *reinterpret_cast<const float4*>(&W_hh[(size_t)kk * HH + jq * 4]);
        float4 vf = *reinterpret_cast<const float4*>(&W_hh[(size_t)(HH + kk) * HH + jq * 4]);
        *reinterpret_cast<float4*>(&Wi4[(jq * 128 + kk) * 4]) = vi;
        *reinterpret_cast<float4*>(&Wf4[(jq * 128 + kk) * 4]) = vf;
    }

    // register pairs for gates g, o on own j-window
    ull wg2[16], wo2[16];
    {
        const float* gp = &W_hh[(size_t)(2*HH + k) * HH + jb];
        const float* op = &W_hh[(size_t)(3*HH + k) * HH + jb];
#pragma unroll
        for (int m = 0; m < 8; ++m) {
            ulonglong2 a = *reinterpret_cast<const ulonglong2*>(gp + m*4);
            wg2[m*2] = a.x; wg2[m*2+1] = a.y;
            ulonglong2 b = *reinterpret_cast<const ulonglong2*>(op + m*4);
            wo2[m*2] = b.x; wo2[m*2+1] = b.y;
        }
    }

    const int mylen = (jg < 2) ? lengths[b0 + jg] : 0;
    float cme = 0.f, hme = 0.f;

    if (tid < 512) hs[tid] = 0.f;       // both buffers
    __syncthreads();

    float gxc0, gxc1;
    {
        const float* r = g_gx + (size_t)b0 * G4;
        gxc0 = r[jg*HH + k];
        gxc1 = r[G4 + jg*HH + k];
    }

    for (int t = 0; t < TT; ++t) {
        // branchless next-step gx prefetch
        int tn = (t + 1 < TT) ? (t + 1) : t;
        const float* rg = g_gx + (size_t)(tn * BB + b0) * G4;
        float gxn0 = rg[jg*HH + k];
        float gxn1 = rg[G4 + jg*HH + k];

        ull acc[4][2];
#pragma unroll
        for (int gi = 0; gi < 4; ++gi) {
            acc[gi][0] = pack2((gi == jg) ? gxc0 : 0.f, 0.f);
            acc[gi][1] = pack2((gi == jg) ? gxc1 : 0.f, 0.f);
        }

        const float* hb = hs + (t & 1) * 256;

#pragma unroll
        for (int q = 0; q < 8; ++q) {
            ulonglong2 hp0 = *reinterpret_cast<const ulonglong2*>(&hb[jb + q*4]);
            ulonglong2 hp1 = *reinterpret_cast<const ulonglong2*>(&hb[128 + jb + q*4]);
            ulonglong2 wi = *reinterpret_cast<const ulonglong2*>(&Wi4[((jbq + q) * 128 + k) * 4]);
            ulonglong2 wf = *reinterpret_cast<const ulonglong2*>(&Wf4[((jbq + q) * 128 + k) * 4]);

            acc[0][0] = fma2(wi.x, hp0.x, acc[0][0]);
            acc[0][0] = fma2(wi.y, hp0.y, acc[0][0]);
            acc[0][1] = fma2(wi.x, hp1.x, acc[0][1]);
            acc[0][1] = fma2(wi.y, hp1.y, acc[0][1]);

            acc[1][0] = fma2(wf.x, hp0.x, acc[1][0]);
            acc[1][0] = fma2(wf.y, hp0.y, acc[1][0]);
            acc[1][1] = fma2(wf.x, hp1.x, acc[1][1]);
            acc[1][1] = fma2(wf.y, hp1.y, acc[1][1]);

            acc[2][0] = fma2(wg2[2*q],   hp0.x, acc[2][0]);
            acc[2][0] = fma2(wg2[2*q+1], hp0.y, acc[2][0]);
            acc[2][1] = fma2(wg2[2*q],   hp1.x, acc[2][1]);
            acc[2][1] = fma2(wg2[2*q+1], hp1.y, acc[2][1]);

            acc[3][0] = fma2(wo2[2*q],   hp0.x, acc[3][0]);
            acc[3][0] = fma2(wo2[2*q+1], hp0.y, acc[3][0]);
            acc[3][1] = fma2(wo2[2*q],   hp1.x, acc[3][1]);
            acc[3][1] = fma2(wo2[2*q+1], hp1.y, acc[3][1]);
        }

        // warp-internal reduction across the 4 j-groups (lanes xor 8, 16)
        float s[8];
#pragma unroll
        for (int gi = 0; gi < 4; ++gi) {
            s[gi*2]   = sum2(acc[gi][0]);
            s[gi*2+1] = sum2(acc[gi][1]);
        }
#pragma unroll
        for (int v = 0; v < 8; ++v) {
            s[v] += __shfl_xor_sync(0xFFFFFFFF, s[v], 8);
            s[v] += __shfl_xor_sync(0xFFFFFFFF, s[v], 16);
        }

        // elementwise: lanes 0-7 (jg0) -> batch0, lanes 8-15 (jg1) -> batch1
        if (jg < 2) {
            float ig = sigf(s[0 + jg]);
            float fg = sigf(s[2 + jg]);
            float gg = tanhf_fast(s[4 + jg]);
            float og = sigf(s[6 + jg]);
            float cn = fg * cme + ig * gg;
            float hn = og * tanhf_fast(cn);
            if (t < mylen) { cme = cn; hme = hn; }
            hs[((t + 1) & 1) * 256 + jg * 128 + k] = hme;
        }
        __syncthreads();

        gxc0 = gxn0; gxc1 = gxn1;
    }

    if (jg < 2) g_h[(b0 + jg) * HH + k] = hme;
}

// ======================================================================
// Kernel 3: fc -- warp per batch, coalesced h reads, shfl reduction.
// ======================================================================
__global__ void __launch_bounds__(256) fc_kernel(
    const float* __restrict__ fc_w,
    const float* __restrict__ fc_b,
    float* __restrict__ out)
{
    __shared__ float wsm[CC * HH];
    __shared__ float bsm2[CC];
    int tid = threadIdx.x;
    for (int i = tid; i < CC * HH; i += 256) wsm[i] = fc_w[i];
    if (tid < CC) bsm2[tid] = fc_b[tid];
    __syncthreads();

    const int w    = tid >> 5;
    const int lane = tid & 31;
    const int b    = blockIdx.x * 8 + w;

    float4 hv = *reinterpret_cast<const float4*>(&g_h[b * HH + lane * 4]);

    float s[CC];
#pragma unroll
    for (int c = 0; c < CC; ++c) {
        const float* wr = &wsm[c * HH + lane * 4];
        s[c] = hv.x * wr[0] + hv.y * wr[1] + hv.z * wr[2] + hv.w * wr[3];
#pragma unroll
        for (int off = 16; off > 0; off >>= 1)
            s[c] += __shfl_xor_sync(0xFFFFFFFF, s[c], off);
    }
    if (lane == 0) {
#pragma unroll
        for (int c = 0; c < CC; ++c)
            out[b * CC + c] = s[c] + bsm2[c];
    }
}

// ======================================================================
extern "C" void kernel_launch(void* const* d_in, const int* in_sizes, int n_in,
                              void* d_out, int out_size)
{
    const float* x     = (const float*)d_in[0];
    const float* W_ih  = (const float*)d_in[1];
    const float* W_hh  = (const float*)d_in[2];
    const float* b_ih  = (const float*)d_in[3];
    const float* b_hh  = (const float*)d_in[4];
    const float* fc_w  = (const float*)d_in[5];
    const float* fc_b  = (const float*)d_in[6];
    const int*   lens  = (const int*)d_in[7];
    float* out = (float*)d_out;

    cudaFuncSetAttribute(gx_kernel, cudaFuncAttributeMaxDynamicSharedMemorySize, SMEM_GX);
    cudaFuncSetAttribute(lstm_kernel, cudaFuncAttributeMaxDynamicSharedMemorySize, SMEM_LS);

    size_t total = NXP + NWP;
    int pblocks = (int)((total + 255) / 256);
    precvt_kernel<<<pblocks, 256>>>(x, W_ih);

    dim3 g1(G4 / 128, (TT * BB) / 128);   // (4, 1024): N fast -> A-tile L2 reuse
    gx_kernel<<<g1, 256, SMEM_GX>>>(b_ih, b_hh);

    lstm_kernel<<<BB / 2, 512, SMEM_LS>>>(W_hh, lens);

    fc_kernel<<<32, 256>>>(fc_w, fc_b, out);
}